// round 10
// baseline (speedup 1.0000x reference)
#include <cuda_runtime.h>
#include <math.h>
#include <stdint.h>

// Problem constants (fixed by dataset)
#define B_   16
#define S_   128
#define D_   128
#define E_   64
#define T_   128
#define NTOK (B_ * S_)   // 2048
#define NB   128         // grid: one CTA per t (tde) / per p (c)
#define NT   256         // 8 warps
#define NW   8

// ----------------------------------------------------------------------------
// Global scratch (allocation-free)
// ----------------------------------------------------------------------------
__device__ float g_tde   [NTOK * T_];   // tanh'd tde for active tokens (per level)
__device__ float g_delta [NTOK * D_];   // level-1 delta
__device__ float g_delta2[NTOK * D_];   // level-2 delta (separate: avoids alias)

// grid barrier state
__device__ unsigned          g_barCount = 0;
__device__ volatile unsigned g_barGen   = 0;

__device__ __forceinline__ void gsync(unsigned nb, unsigned& gen) {
    __syncthreads();
    if (threadIdx.x == 0) {
        __threadfence();
        unsigned arr = atomicAdd(&g_barCount, 1u);
        if (arr == nb - 1u) {
            g_barCount = 0u;
            __threadfence();
            g_barGen = gen + 1u;
        } else {
            while (g_barGen == gen) __nanosleep(64);
        }
    }
    gen += 1u;
    __syncthreads();
}

// ----------------------------------------------------------------------------
// Smem layout (float offsets)
// ----------------------------------------------------------------------------
#define OFF_W1   0        // 8192  : W1[bid,:,:]  (128 x 64)       [bulk copy]
#define OFF_W2   8192     // 16384 : W2[bid,:,:]  (128 x 128)      [bulk copy]
#define OFF_HS   24576    // 2048 ints : heads
#define OFF_L1   26624    // 2048 ints : list1
#define OFF_L2   28672    // 2048 ints : list2
#define OFF_TOKB 30720    // 8 warps x 2 tokens x 128
#define OFF_DEPB 32768    // 8 warps x 2 tokens x 64
#define OFF_BASE 33792    // 128
#define OFF_WRS  33920    // 128
#define OFF_CNT  34048    // 2 ints
#define OFF_RED  34052    // 4
#define OFF_MBAR 34056    // mbarrier (8 bytes, 8B-aligned: 34056*4 % 8 == 0)
#define SMEM_FLOATS 34064
#define SMEM_BYTES  (SMEM_FLOATS * 4)

#define W_BYTES ((D_ * E_ + D_ * T_) * 4)   // 98304 bytes per CTA

__device__ __forceinline__ uint32_t smem_u32(const void* p) {
    return (uint32_t)__cvta_generic_to_shared(p);
}

__device__ __forceinline__ void mbar_wait_parity0(uint32_t mb) {
    asm volatile(
        "{\n\t"
        ".reg .pred P1;\n\t"
        "WAIT_%=:\n\t"
        "mbarrier.try_wait.parity.acquire.cta.shared::cta.b64 P1, [%0], 0, 0x989680;\n\t"
        "@P1 bra.uni DONE_%=;\n\t"
        "bra.uni WAIT_%=;\n\t"
        "DONE_%=:\n\t"
        "}"
        :: "r"(mb) : "memory");
}

// Build tok1 row for token idx into tb (lane covers d = lane + 32k).
// tok1[idx] = base + sum_{j asc: h[j]==pos(idx)} delta1[j]   (fixed j order)
__device__ __forceinline__ void build_tok1(float* tb, int idx, const int* hs,
                                           const float* base_s, int lane) {
    int b7 = idx & ~(S_ - 1), i = idx & (S_ - 1);
    float v0 = base_s[lane], v1 = base_s[lane + 32];
    float v2 = base_s[lane + 64], v3 = base_s[lane + 96];
    #pragma unroll 4
    for (int j = 0; j < S_; ++j) {
        if (hs[b7 + j] == i) {
            const float* dr = g_delta + (size_t)(b7 + j) * D_;
            v0 += dr[lane];      v1 += dr[lane + 32];
            v2 += dr[lane + 64]; v3 += dr[lane + 96];
        }
    }
    tb[lane] = v0; tb[lane + 32] = v1; tb[lane + 64] = v2; tb[lane + 96] = v3;
}

// ----------------------------------------------------------------------------
__global__ void __launch_bounds__(NT, 1)
fused_kernel(const float* __restrict__ tok_table,
             const float* __restrict__ dep_table,
             const float* __restrict__ W1,
             const float* __restrict__ b1,
             const float* __restrict__ W2,
             const float* __restrict__ b2,
             const float* __restrict__ wr,
             const float* __restrict__ br,
             const int*   __restrict__ tokens,
             const int*   __restrict__ dep_types,
             const int*   __restrict__ heads,
             float*       __restrict__ out) {
    extern __shared__ float smem[];
    float* W1s    = smem + OFF_W1;
    float* W2s    = smem + OFF_W2;
    int*   hs     = (int*)(smem + OFF_HS);
    int*   l1     = (int*)(smem + OFF_L1);
    int*   l2     = (int*)(smem + OFF_L2);
    float* tokb   = smem + OFF_TOKB;
    float* depb   = smem + OFF_DEPB;
    float* base_s = smem + OFF_BASE;
    float* wrs    = smem + OFF_WRS;
    int*   cnts   = (int*)(smem + OFF_CNT);
    float* red    = smem + OFF_RED;

    const int bid  = blockIdx.x;
    const int tid  = threadIdx.x;
    const int lane = tid & 31;
    const int w    = tid >> 5;
    const unsigned nb = gridDim.x;

    unsigned gen = g_barGen;   // read before any bump -> race-free

    // ------- Kick off async bulk weight copy FIRST (overlaps all setup) ------
    const uint32_t mb = smem_u32(smem + OFF_MBAR);
    if (tid == 0) {
        asm volatile("mbarrier.init.shared.b64 [%0], %1;" :: "r"(mb), "r"(1) : "memory");
        asm volatile("fence.proxy.async.shared::cta;" ::: "memory");
        asm volatile("mbarrier.arrive.expect_tx.shared.b64 _, [%0], %1;"
                     :: "r"(mb), "r"((uint32_t)W_BYTES) : "memory");
        asm volatile(
            "cp.async.bulk.shared::cta.global.mbarrier::complete_tx::bytes [%0], [%1], %2, [%3];"
            :: "r"(smem_u32(W1s)), "l"(W1 + (size_t)bid * D_ * E_),
               "r"((uint32_t)(D_ * E_ * 4)), "r"(mb) : "memory");
        asm volatile(
            "cp.async.bulk.shared::cta.global.mbarrier::complete_tx::bytes [%0], [%1], %2, [%3];"
            :: "r"(smem_u32(W2s)), "l"(W2 + (size_t)bid * D_ * T_),
               "r"((uint32_t)(D_ * T_ * 4)), "r"(mb) : "memory");
    }

    // ---------------- Setup under the copy: heads, consts, lists, zero-out ---
    {
        const int4* hsrc = (const int4*)heads;
        int4* hd = (int4*)hs;
        #pragma unroll
        for (int k = tid; k < NTOK / 4; k += NT) hd[k] = hsrc[k];
        if (tid < 128) wrs[tid] = wr[tid];
        if (tid == 0) { cnts[0] = 0; cnts[1] = 0; }
    }
    __syncthreads();   // also makes mbarrier init visible to all threads

    if (tid < 128) {
        float v = wrs[tid];
        #pragma unroll
        for (int o = 16; o; o >>= 1) v += __shfl_down_sync(0xffffffffu, v, o);
        if (lane == 0) red[w] = v;
    }
    __syncthreads();
    if (tid < 128) {
        float swr = red[0] + red[1] + red[2] + red[3];
        base_s[tid] = swr * tanhf(b2[tid]) + br[0];
    }
    // per-CTA redundant list build (order-independent results)
    for (int idx = tid; idx < NTOK; idx += NT) {
        int b7 = idx & ~(S_ - 1);
        int h1 = hs[idx];
        int h2 = hs[b7 + h1];
        int h3 = hs[b7 + h2];
        if (h2 == 0) l2[atomicAdd(&cnts[1], 1)] = idx;
        if (h3 == 0) l1[atomicAdd(&cnts[0], 1)] = idx;
    }
    // early zero-write of masked output rows (overlaps with bulk copy)
    for (int rr = (tid >> 7); rr < NTOK / NB; rr += 2) {
        int r = bid + NB * rr;
        if (hs[r] != 0) out[(size_t)r * D_ + (tid & 127)] = 0.f;
    }

    // ---------------- Wait for weights, then compute --------------------------
    mbar_wait_parity0(mb);
    __syncthreads();

    const int cnt1 = cnts[0];
    const int cnt2 = cnts[1];
    const float b1t  = b1[bid];
    const float b2p  = b2[bid];
    const float cbgp = tanhf(b2p);

    for (int level = 1; level <= 2; ++level) {
        const int  cnt  = (level == 1) ? cnt1 : cnt2;
        const int* list = (level == 1) ? l1   : l2;
        float* dst      = (level == 1) ? g_delta : g_delta2;
        const bool reuse = (cnt <= 2 * NW);   // tokb survives into c phase

        // ---------- tde phase: CTA t = bid, 2 tokens per warp -----------------
        for (int g = w; 2 * g < cnt; g += NW) {
            int idx0 = list[2 * g];
            int idx1 = (2 * g + 1 < cnt) ? list[2 * g + 1] : -1;
            float* tb0 = tokb + (w * 2 + 0) * 128;
            float* tb1 = tokb + (w * 2 + 1) * 128;
            float* db0 = depb + (w * 2 + 0) * 64;
            float* db1 = depb + (w * 2 + 1) * 64;

            if (level == 1) {
                const float* tr0 = tok_table + (size_t)tokens[idx0] * D_;
                ((float4*)tb0)[lane] = ((const float4*)tr0)[lane];
                if (idx1 >= 0) {
                    const float* tr1 = tok_table + (size_t)tokens[idx1] * D_;
                    ((float4*)tb1)[lane] = ((const float4*)tr1)[lane];
                } else {
                    ((float4*)tb1)[lane] = make_float4(0.f, 0.f, 0.f, 0.f);
                }
            } else {
                build_tok1(tb0, idx0, hs, base_s, lane);
                if (idx1 >= 0) build_tok1(tb1, idx1, hs, base_s, lane);
                else { tb1[lane] = 0.f; tb1[lane+32] = 0.f; tb1[lane+64] = 0.f; tb1[lane+96] = 0.f; }
            }
            if (lane < 16) {
                const float* dr0 = dep_table + (size_t)dep_types[idx0] * E_;
                ((float4*)db0)[lane] = ((const float4*)dr0)[lane];
                if (idx1 >= 0) {
                    const float* dr1 = dep_table + (size_t)dep_types[idx1] * E_;
                    ((float4*)db1)[lane] = ((const float4*)dr1)[lane];
                } else {
                    ((float4*)db1)[lane] = make_float4(0.f, 0.f, 0.f, 0.f);
                }
            }
            __syncwarp();

            float de00 = db0[lane], de01 = db0[lane + 32];
            float de10 = db1[lane], de11 = db1[lane + 32];
            float a00 = 0.f, a01 = 0.f, a10 = 0.f, a11 = 0.f;
            #pragma unroll 8
            for (int d = 0; d < D_; ++d) {
                float w0 = W1s[d * E_ + lane];
                float w1 = W1s[d * E_ + lane + 32];
                float t0 = tb0[d];
                float t1 = tb1[d];
                a00 = fmaf(t0 * de00, w0, a00);
                a01 = fmaf(t0 * de01, w1, a01);
                a10 = fmaf(t1 * de10, w0, a10);
                a11 = fmaf(t1 * de11, w1, a11);
            }
            float s0 = a00 + a01, s1 = a10 + a11;
            #pragma unroll
            for (int o = 16; o; o >>= 1) {
                s0 += __shfl_down_sync(0xffffffffu, s0, o);
                s1 += __shfl_down_sync(0xffffffffu, s1, o);
            }
            if (lane == 0) {
                g_tde[(size_t)idx0 * T_ + bid] = tanhf(s0 + b1t);
                if (idx1 >= 0) g_tde[(size_t)idx1 * T_ + bid] = tanhf(s1 + b1t);
            }
            __syncwarp();
        }
        gsync(nb, gen);

        // ---------- c + delta phase: CTA p = bid, 2 tokens per warp -----------
        for (int g = w; 2 * g < cnt; g += NW) {
            int idx0 = list[2 * g];
            int idx1 = (2 * g + 1 < cnt) ? list[2 * g + 1] : -1;
            float* tb0 = tokb + (w * 2 + 0) * 128;
            float* tb1 = tokb + (w * 2 + 1) * 128;

            if (!reuse) {   // tokb stale (multiple groups per warp): rebuild
                if (level == 1) {
                    const float* tr0 = tok_table + (size_t)tokens[idx0] * D_;
                    ((float4*)tb0)[lane] = ((const float4*)tr0)[lane];
                    if (idx1 >= 0) {
                        const float* tr1 = tok_table + (size_t)tokens[idx1] * D_;
                        ((float4*)tb1)[lane] = ((const float4*)tr1)[lane];
                    } else {
                        ((float4*)tb1)[lane] = make_float4(0.f, 0.f, 0.f, 0.f);
                    }
                } else {
                    build_tok1(tb0, idx0, hs, base_s, lane);
                    if (idx1 >= 0) build_tok1(tb1, idx1, hs, base_s, lane);
                    else { tb1[lane] = 0.f; tb1[lane+32] = 0.f; tb1[lane+64] = 0.f; tb1[lane+96] = 0.f; }
                }
                __syncwarp();
            }

            float4 tv0 = *(const float4*)(g_tde + (size_t)idx0 * T_ + lane * 4);
            float4 tv1 = (idx1 >= 0)
                ? *(const float4*)(g_tde + (size_t)idx1 * T_ + lane * 4)
                : make_float4(0.f, 0.f, 0.f, 0.f);

            float a00 = 0.f, a01 = 0.f, a02 = 0.f, a03 = 0.f;
            float a10 = 0.f, a11 = 0.f, a12 = 0.f, a13 = 0.f;
            const float4* W2s4 = (const float4*)W2s;
            #pragma unroll 4
            for (int d = 0; d < D_; ++d) {
                float4 wv = W2s4[d * 32 + lane];
                float t0 = tb0[d];
                float t1 = tb1[d];
                a00 = fmaf(t0, wv.x, a00); a01 = fmaf(t0, wv.y, a01);
                a02 = fmaf(t0, wv.z, a02); a03 = fmaf(t0, wv.w, a03);
                a10 = fmaf(t1, wv.x, a10); a11 = fmaf(t1, wv.y, a11);
                a12 = fmaf(t1, wv.z, a12); a13 = fmaf(t1, wv.w, a13);
            }
            float s0 = a00 * tv0.x + a01 * tv0.y + a02 * tv0.z + a03 * tv0.w;
            float s1 = a10 * tv1.x + a11 * tv1.y + a12 * tv1.z + a13 * tv1.w;
            #pragma unroll
            for (int o = 16; o; o >>= 1) {
                s0 += __shfl_down_sync(0xffffffffu, s0, o);
                s1 += __shfl_down_sync(0xffffffffu, s1, o);
            }
            if (lane == 0) {
                dst[(size_t)idx0 * D_ + bid] =
                    wrs[idx0 & (S_ - 1)] * (tanhf(s0 + b2p) - cbgp);
                if (idx1 >= 0)
                    dst[(size_t)idx1 * D_ + bid] =
                        wrs[idx1 & (S_ - 1)] * (tanhf(s1 + b2p) - cbgp);
            }
            __syncwarp();
        }
        gsync(nb, gen);
    }

    // -------- Output tail: root rows only (zeros written in phase 0) ----------
    for (int rr = (tid >> 7); rr < NTOK / NB; rr += 2) {
        int r = bid + NB * rr;
        if (hs[r] != 0) continue;
        int col = tid & 127;
        int b7 = r & ~(S_ - 1), i = r & (S_ - 1);
        float v = base_s[col];
        #pragma unroll 4
        for (int j = 0; j < S_; ++j)
            if (hs[b7 + j] == i)
                v += g_delta2[(size_t)(b7 + j) * D_ + col];
        out[(size_t)r * D_ + col] = v;
    }
}

// ----------------------------------------------------------------------------
extern "C" void kernel_launch(void* const* d_in, const int* in_sizes, int n_in,
                              void* d_out, int out_size) {
    const float* tok_table = (const float*)d_in[0];
    const float* dep_table = (const float*)d_in[1];
    const float* W1        = (const float*)d_in[2];
    const float* b1        = (const float*)d_in[3];
    const float* W2        = (const float*)d_in[4];
    const float* b2        = (const float*)d_in[5];
    const float* wr        = (const float*)d_in[6];
    const float* br        = (const float*)d_in[7];
    const int*   tokens    = (const int*)  d_in[8];
    const int*   dep_types = (const int*)  d_in[9];
    const int*   heads     = (const int*)  d_in[10];
    float*       out       = (float*)d_out;
    (void)in_sizes; (void)n_in; (void)out_size;

    cudaFuncSetAttribute(fused_kernel,
                         cudaFuncAttributeMaxDynamicSharedMemorySize,
                         SMEM_BYTES);
    fused_kernel<<<NB, NT, SMEM_BYTES>>>(tok_table, dep_table, W1, b1, W2, b2,
                                         wr, br, tokens, dep_types, heads, out);
}

// round 12
// speedup vs baseline: 1.4815x; 1.4815x over previous
#include <cuda_runtime.h>
#include <math.h>

// Problem constants (fixed by dataset)
#define B_   16
#define S_   128
#define D_   128
#define E_   64
#define T_   128
#define NTOK (B_ * S_)   // 2048
#define NB   128         // grid: one CTA per t (tde) / per p (c)
#define NT   512         // 16 warps (4 per SMSP)
#define NW   16

// ----------------------------------------------------------------------------
// Global scratch (allocation-free)
// ----------------------------------------------------------------------------
__device__ float g_tde   [NTOK * T_];   // tanh'd tde for active tokens (per level)
__device__ float g_delta [NTOK * D_];   // level-1 delta
__device__ float g_delta2[NTOK * D_];   // level-2 delta (separate: avoids alias)

// grid barrier state
__device__ unsigned          g_barCount = 0;
__device__ volatile unsigned g_barGen   = 0;

__device__ __forceinline__ void gsync(unsigned nb, unsigned& gen) {
    __syncthreads();
    if (threadIdx.x == 0) {
        __threadfence();
        unsigned arr = atomicAdd(&g_barCount, 1u);
        if (arr == nb - 1u) {
            g_barCount = 0u;
            __threadfence();
            g_barGen = gen + 1u;
        } else {
            while (g_barGen == gen) __nanosleep(64);
        }
    }
    gen += 1u;
    __syncthreads();
}

// ----------------------------------------------------------------------------
// Smem layout (float offsets)
// ----------------------------------------------------------------------------
#define OFF_W1   0        // 8192  : W1[bid,:,:]  (128 x 64)
#define OFF_W2   8192     // 16384 : W2[bid,:,:]  (128 x 128)
#define OFF_HS   24576    // 2048 ints : heads
#define OFF_L1   26624    // 2048 ints : list1
#define OFF_L2   28672    // 2048 ints : list2
#define OFF_TOKB 30720    // 16 warps x 128
#define OFF_DEPB 32768    // 16 warps x 64
#define OFF_BASE 33792    // 128
#define OFF_WRS  33920    // 128
#define OFF_CNT  34048    // 2 ints
#define OFF_RED  34052    // 4
#define SMEM_FLOATS 34064
#define SMEM_BYTES  (SMEM_FLOATS * 4)

// Build tok1 row for token idx into tb (lane covers d = lane + 32k).
// tok1[idx] = base + sum_{j asc: h[j]==pos(idx)} delta1[j]   (fixed j order)
__device__ __forceinline__ void build_tok1(float* tb, int idx, const int* hs,
                                           const float* base_s, int lane) {
    int b7 = idx & ~(S_ - 1), i = idx & (S_ - 1);
    float v0 = base_s[lane], v1 = base_s[lane + 32];
    float v2 = base_s[lane + 64], v3 = base_s[lane + 96];
    #pragma unroll 4
    for (int j = 0; j < S_; ++j) {
        if (hs[b7 + j] == i) {
            const float* dr = g_delta + (size_t)(b7 + j) * D_;
            v0 += dr[lane];      v1 += dr[lane + 32];
            v2 += dr[lane + 64]; v3 += dr[lane + 96];
        }
    }
    tb[lane] = v0; tb[lane + 32] = v1; tb[lane + 64] = v2; tb[lane + 96] = v3;
}

// ----------------------------------------------------------------------------
__global__ void __launch_bounds__(NT, 1)
fused_kernel(const float* __restrict__ tok_table,
             const float* __restrict__ dep_table,
             const float* __restrict__ W1,
             const float* __restrict__ b1,
             const float* __restrict__ W2,
             const float* __restrict__ b2,
             const float* __restrict__ wr,
             const float* __restrict__ br,
             const int*   __restrict__ tokens,
             const int*   __restrict__ dep_types,
             const int*   __restrict__ heads,
             float*       __restrict__ out) {
    extern __shared__ float smem[];
    float* W1s    = smem + OFF_W1;
    float* W2s    = smem + OFF_W2;
    int*   hs     = (int*)(smem + OFF_HS);
    int*   l1     = (int*)(smem + OFF_L1);
    int*   l2     = (int*)(smem + OFF_L2);
    float* tokb   = smem + OFF_TOKB;
    float* depb   = smem + OFF_DEPB;
    float* base_s = smem + OFF_BASE;
    float* wrs    = smem + OFF_WRS;
    int*   cnts   = (int*)(smem + OFF_CNT);
    float* red    = smem + OFF_RED;

    const int bid  = blockIdx.x;
    const int tid  = threadIdx.x;
    const int lane = tid & 31;
    const int w    = tid >> 5;
    const unsigned nb = gridDim.x;

    unsigned gen = g_barGen;   // read before any bump -> race-free

    // ---------------- Phase 0 (no cross-CTA deps): heads, consts, lists ------
    {
        const int4* hsrc = (const int4*)heads;
        int4* hd = (int4*)hs;
        #pragma unroll
        for (int k = tid; k < NTOK / 4; k += NT) hd[k] = hsrc[k];
        if (tid < 128) wrs[tid] = wr[tid];
        if (tid == 0) { cnts[0] = 0; cnts[1] = 0; }
    }
    __syncthreads();

    if (tid < 128) {
        float v = wrs[tid];
        #pragma unroll
        for (int o = 16; o; o >>= 1) v += __shfl_down_sync(0xffffffffu, v, o);
        if (lane == 0) red[w] = v;
    }
    __syncthreads();
    if (tid < 128) {
        float swr = red[0] + red[1] + red[2] + red[3];
        base_s[tid] = swr * tanhf(b2[tid]) + br[0];
    }
    // per-CTA redundant list build (order-independent results)
    for (int idx = tid; idx < NTOK; idx += NT) {
        int b7 = idx & ~(S_ - 1);
        int h1 = hs[idx];
        int h2 = hs[b7 + h1];
        int h3 = hs[b7 + h2];
        if (h2 == 0) l2[atomicAdd(&cnts[1], 1)] = idx;
        if (h3 == 0) l1[atomicAdd(&cnts[0], 1)] = idx;
    }
    // weight preload (warp-parallel LDG: proven faster than bulk-DMA here)
    {
        const float4* s1 = (const float4*)(W1 + (size_t)bid * D_ * E_);
        float4* d1 = (float4*)W1s;
        #pragma unroll
        for (int k = tid; k < (D_ * E_) / 4; k += NT) d1[k] = s1[k];
        const float4* s2 = (const float4*)(W2 + (size_t)bid * D_ * T_);
        float4* d2 = (float4*)W2s;
        #pragma unroll
        for (int k = tid; k < (D_ * T_) / 4; k += NT) d2[k] = s2[k];
    }
    // early zero-write of masked output rows (overlaps with preload latency)
    for (int rr = (tid >> 7); rr < NTOK / NB; rr += NT / 128) {
        int r = bid + NB * rr;
        if (hs[r] != 0) out[(size_t)r * D_ + (tid & 127)] = 0.f;
    }
    __syncthreads();

    const int cnt1 = cnts[0];
    const int cnt2 = cnts[1];
    const float b1t  = b1[bid];
    const float b2p  = b2[bid];
    const float cbgp = tanhf(b2p);

    for (int level = 1; level <= 2; ++level) {
        const int  cnt  = (level == 1) ? cnt1 : cnt2;
        const int* list = (level == 1) ? l1   : l2;
        float* dst      = (level == 1) ? g_delta : g_delta2;
        const bool reuse = (cnt <= NW);   // tokb survives into c phase

        // ---------- tde phase: CTA t = bid, one token per warp ----------------
        for (int mi = w; mi < cnt; mi += NW) {
            int idx = list[mi];
            float* tb = tokb + w * 128;
            float* db = depb + w * 64;

            if (level == 1) {
                const float* tr = tok_table + (size_t)tokens[idx] * D_;
                ((float4*)tb)[lane] = ((const float4*)tr)[lane];
            } else {
                build_tok1(tb, idx, hs, base_s, lane);
            }
            if (lane < 16) {
                const float* dr = dep_table + (size_t)dep_types[idx] * E_;
                ((float4*)db)[lane] = ((const float4*)dr)[lane];
            }
            __syncwarp();

            float de0 = db[lane], de1 = db[lane + 32];
            float a0 = 0.f, a1 = 0.f;
            #pragma unroll 8
            for (int d = 0; d < D_; ++d) {
                float t = tb[d];
                a0 = fmaf(t * de0, W1s[d * E_ + lane], a0);
                a1 = fmaf(t * de1, W1s[d * E_ + lane + 32], a1);
            }
            float s = a0 + a1;
            #pragma unroll
            for (int o = 16; o; o >>= 1)
                s += __shfl_down_sync(0xffffffffu, s, o);
            if (lane == 0) g_tde[(size_t)idx * T_ + bid] = tanhf(s + b1t);
            __syncwarp();
        }
        gsync(nb, gen);

        // ---------- c + delta phase: CTA p = bid, one token per warp ----------
        for (int mi = w; mi < cnt; mi += NW) {
            int idx = list[mi];
            float* tb = tokb + w * 128;

            if (!reuse) {   // tokb stale (multiple passes): rebuild
                if (level == 1) {
                    const float* tr = tok_table + (size_t)tokens[idx] * D_;
                    ((float4*)tb)[lane] = ((const float4*)tr)[lane];
                } else {
                    build_tok1(tb, idx, hs, base_s, lane);
                }
                __syncwarp();
            }

            float4 tv = *(const float4*)(g_tde + (size_t)idx * T_ + lane * 4);

            float a0 = 0.f, a1 = 0.f, a2 = 0.f, a3 = 0.f;
            const float4* W2s4 = (const float4*)W2s;
            #pragma unroll 4
            for (int d = 0; d < D_; ++d) {
                float4 wv = W2s4[d * 32 + lane];
                float t = tb[d];
                a0 = fmaf(t, wv.x, a0);
                a1 = fmaf(t, wv.y, a1);
                a2 = fmaf(t, wv.z, a2);
                a3 = fmaf(t, wv.w, a3);
            }
            float s = a0 * tv.x + a1 * tv.y + a2 * tv.z + a3 * tv.w;
            #pragma unroll
            for (int o = 16; o; o >>= 1)
                s += __shfl_down_sync(0xffffffffu, s, o);
            if (lane == 0) {
                dst[(size_t)idx * D_ + bid] =
                    wrs[idx & (S_ - 1)] * (tanhf(s + b2p) - cbgp);
            }
            __syncwarp();
        }
        gsync(nb, gen);
    }

    // -------- Output tail: root rows only (zeros written in phase 0) ----------
    for (int rr = (tid >> 7); rr < NTOK / NB; rr += NT / 128) {
        int r = bid + NB * rr;
        if (hs[r] != 0) continue;
        int col = tid & 127;
        int b7 = r & ~(S_ - 1), i = r & (S_ - 1);
        float v = base_s[col];
        #pragma unroll 4
        for (int j = 0; j < S_; ++j)
            if (hs[b7 + j] == i)
                v += g_delta2[(size_t)(b7 + j) * D_ + col];
        out[(size_t)r * D_ + col] = v;
    }
}

// ----------------------------------------------------------------------------
extern "C" void kernel_launch(void* const* d_in, const int* in_sizes, int n_in,
                              void* d_out, int out_size) {
    const float* tok_table = (const float*)d_in[0];
    const float* dep_table = (const float*)d_in[1];
    const float* W1        = (const float*)d_in[2];
    const float* b1        = (const float*)d_in[3];
    const float* W2        = (const float*)d_in[4];
    const float* b2        = (const float*)d_in[5];
    const float* wr        = (const float*)d_in[6];
    const float* br        = (const float*)d_in[7];
    const int*   tokens    = (const int*)  d_in[8];
    const int*   dep_types = (const int*)  d_in[9];
    const int*   heads     = (const int*)  d_in[10];
    float*       out       = (float*)d_out;
    (void)in_sizes; (void)n_in; (void)out_size;

    cudaFuncSetAttribute(fused_kernel,
                         cudaFuncAttributeMaxDynamicSharedMemorySize,
                         SMEM_BYTES);
    fused_kernel<<<NB, NT, SMEM_BYTES>>>(tok_table, dep_table, W1, b1, W2, b2,
                                         wr, br, tokens, dep_types, heads, out);
}